// round 15
// baseline (speedup 1.0000x reference)
#include <cuda_runtime.h>
#include <stdint.h>

#define N_POS 8192
#define N_NEG 4000u
#define N_TOT (N_POS + N_POS * (int)N_NEG)  // 32,776,192 (divisible by 8)
#define N_VEC (N_TOT / 4)                   // 8,194,048
#define N_VEC8 (N_TOT / 8)                  // 4,097,024

#define HIST_WORDS (N_POS / 2)              // 4096 packed u16x2 words

#define P2_BLOCKS 592
#define P2_THREADS 384                      // 4 blocks/SM, 42-reg budget for prefetch

// Scratch (allocation-free rule: __device__ globals)
__device__ float          g_pos[N_POS];
__device__ unsigned short g_rowid[N_TOT];          // 65.55 MB
__device__ unsigned int   g_hist[HIST_WORDS];      // packed u16x2 (R4-proven flush)

// ---------------------------------------------------------------------------
// Pass 1 (R4 body, 4096 blocks): scan idx (int32) once. Emit u16 row-id per
// element (0xFFFF = pos), scatter the 8192 pos values, zero the histogram.
// ---------------------------------------------------------------------------
__global__ void __launch_bounds__(256) mrr_pass1(
    const float* __restrict__ val, const int* __restrict__ idx)
{
    const unsigned int tid = blockIdx.x * blockDim.x + threadIdx.x;
    if (tid < HIST_WORDS) g_hist[tid] = 0u;

    const unsigned int stride = gridDim.x * blockDim.x;
    const int4* __restrict__ idx4 = (const int4*)idx;
    ushort4* __restrict__ rid4 = (ushort4*)g_rowid;

    #pragma unroll 4
    for (unsigned int v = tid; v < N_VEC; v += stride) {
        int4 q = idx4[v];
        unsigned int j0 = (unsigned int)q.x;
        unsigned int j1 = (unsigned int)q.y;
        unsigned int j2 = (unsigned int)q.z;
        unsigned int j3 = (unsigned int)q.w;
        unsigned int base = v * 4u;

        ushort4 r;
        if (j0 < N_POS) { r.x = 0xFFFFu; g_pos[j0] = val[base + 0]; }
        else            { r.x = (unsigned short)((j0 - N_POS) / N_NEG); }
        if (j1 < N_POS) { r.y = 0xFFFFu; g_pos[j1] = val[base + 1]; }
        else            { r.y = (unsigned short)((j1 - N_POS) / N_NEG); }
        if (j2 < N_POS) { r.z = 0xFFFFu; g_pos[j2] = val[base + 2]; }
        else            { r.z = (unsigned short)((j2 - N_POS) / N_NEG); }
        if (j3 < N_POS) { r.w = 0xFFFFu; g_pos[j3] = val[base + 3]; }
        else            { r.w = (unsigned short)((j3 - N_POS) / N_NEG); }

        rid4[v] = r;
    }
}

// ---------------------------------------------------------------------------
// Pass 2: 8 elems/iter with EXPLICIT 1-deep software pipeline — next
// iteration's rowid+val vectors are in flight while the current 8 elements
// run the LDS-compare-ATOMS chain. 384 thr x 592 blocks = 4 blocks/SM with a
// 42-reg budget (vs the 32-reg straitjacket at 2048 thr/SM).
// Minority-side counting: inc = (v > p) XOR (p <= 0); fixed up in pass 3.
// Per-row total <= 4000 so packed u16 halves never overflow.
// ---------------------------------------------------------------------------
__device__ __forceinline__ void hist_one(
    float v, unsigned int row, const float* s_pos, unsigned int* s_hist)
{
    float p = s_pos[row & 0x1FFFu];
    if (row != 0xFFFFu && ((v > p) != (p <= 0.0f)))
        atomicAdd(&s_hist[row >> 1], 1u << ((row & 1u) << 4));
}

__global__ void __launch_bounds__(P2_THREADS, 4) mrr_pass2(const float* __restrict__ val)
{
    __shared__ float        s_pos[N_POS];       // 32768 B
    __shared__ unsigned int s_hist[HIST_WORDS]; // 16384 B

    const int t = threadIdx.x;
    for (int i = t; i < N_POS; i += P2_THREADS)      s_pos[i]  = g_pos[i];
    for (int i = t; i < HIST_WORDS; i += P2_THREADS) s_hist[i] = 0u;
    __syncthreads();

    const unsigned int stride = gridDim.x * P2_THREADS;
    const float4* __restrict__ v4 = (const float4*)val;
    const uint4*  __restrict__ r8 = (const uint4*)g_rowid;   // 8 u16 per load

    unsigned int v = blockIdx.x * P2_THREADS + t;
    uint4  rr;
    float4 fa, fb;
    bool valid = (v < N_VEC8);
    if (valid) { rr = r8[v]; fa = v4[2 * v]; fb = v4[2 * v + 1]; }

    while (valid) {
        // Prefetch next iteration (overlaps with the chain below)
        unsigned int vn = v + stride;
        bool validn = (vn < N_VEC8);
        uint4  rrn;
        float4 fan, fbn;
        if (validn) { rrn = r8[vn]; fan = v4[2 * vn]; fbn = v4[2 * vn + 1]; }

        hist_one(fa.x, rr.x & 0xFFFFu, s_pos, s_hist);
        hist_one(fa.y, rr.x >> 16,     s_pos, s_hist);
        hist_one(fa.z, rr.y & 0xFFFFu, s_pos, s_hist);
        hist_one(fa.w, rr.y >> 16,     s_pos, s_hist);
        hist_one(fb.x, rr.z & 0xFFFFu, s_pos, s_hist);
        hist_one(fb.y, rr.z >> 16,     s_pos, s_hist);
        hist_one(fb.z, rr.w & 0xFFFFu, s_pos, s_hist);
        hist_one(fb.w, rr.w >> 16,     s_pos, s_hist);

        v = vn; valid = validn;
        if (validn) { rr = rrn; fa = fan; fb = fbn; }
    }
    __syncthreads();

    // R4-proven flush: whole-word atomic add (halves can't carry, <=4000).
    for (int i = t; i < HIST_WORDS; i += P2_THREADS) {
        unsigned int h = s_hist[i];
        if (h) atomicAdd(&g_hist[i], h);
    }
}

// ---------------------------------------------------------------------------
// Pass 3 (R4 + minority fixup): ranks -> sample_mrr, fixed-order mean.
// out[0] = mrr, out[1..8192] = sample_mrr
// ---------------------------------------------------------------------------
__global__ void __launch_bounds__(1024) mrr_pass3(float* __restrict__ out)
{
    __shared__ double ssum[1024];
    const int t = threadIdx.x;
    double local = 0.0;
    for (int r = t; r < N_POS; r += 1024) {
        unsigned int h = g_hist[r >> 1];
        unsigned int c = (r & 1) ? (h >> 16) : (h & 0xFFFFu);
        float p = g_pos[r];
        unsigned int cnt_gt = (p > 0.0f) ? c : (N_NEG - c);
        float s = 1.0f / (float)(1u + cnt_gt);
        out[1 + r] = s;
        local += (double)s;
    }
    ssum[t] = local;
    __syncthreads();
    for (int off = 512; off > 0; off >>= 1) {
        if (t < off) ssum[t] += ssum[t + off];
        __syncthreads();
    }
    if (t == 0) out[0] = (float)(ssum[0] / (double)N_POS);
}

extern "C" void kernel_launch(void* const* d_in, const int* in_sizes, int n_in,
                              void* d_out, int out_size)
{
    const float* val = (const float*)d_in[0];
    const int*   idx = (const int*)d_in[1];
    float*       out = (float*)d_out;

    mrr_pass1<<<4096, 256>>>(val, idx);
    mrr_pass2<<<P2_BLOCKS, P2_THREADS>>>(val);
    mrr_pass3<<<1, 1024>>>(out);
}

// round 16
// speedup vs baseline: 1.0810x; 1.0810x over previous
#include <cuda_runtime.h>
#include <stdint.h>

#define N_POS 8192
#define N_NEG 4000u
#define N_TOT (N_POS + N_POS * (int)N_NEG)  // 32,776,192 (divisible by 4)
#define N_VEC (N_TOT / 4)                   // 8,194,048

#define HIST_WORDS (N_POS / 2)              // 4096 packed u16x2 words

#define P2_BLOCKS 592
#define P2_THREADS 512

// Scratch (allocation-free rule: __device__ globals)
__device__ float          g_pos[N_POS];
__device__ unsigned short g_rowid[N_TOT];          // 65.55 MB -- FITS IN L2 (126MB)
__device__ unsigned int   g_hist[HIST_WORDS];      // packed u16x2 (R4-proven flush)

// ---------------------------------------------------------------------------
// Pass 1 (R4 body + cache hints): scan idx once with STREAMING loads (evict-
// first, so the 131MB idx stream does not flush L2). Rowid stores use default
// policy -> the 65.5MB rowid array stays L2-resident for pass 2.
// Emit u16 row-id per element (0xFFFF = pos), scatter pos values, zero hist.
// ---------------------------------------------------------------------------
__global__ void __launch_bounds__(256) mrr_pass1(
    const float* __restrict__ val, const int* __restrict__ idx)
{
    const unsigned int tid = blockIdx.x * blockDim.x + threadIdx.x;
    if (tid < HIST_WORDS) g_hist[tid] = 0u;

    const unsigned int stride = gridDim.x * blockDim.x;
    const int4* __restrict__ idx4 = (const int4*)idx;
    ushort4* __restrict__ rid4 = (ushort4*)g_rowid;

    #pragma unroll 4
    for (unsigned int v = tid; v < N_VEC; v += stride) {
        int4 q = __ldcs(&idx4[v]);          // streaming: keep L2 clean for rowid
        unsigned int j0 = (unsigned int)q.x;
        unsigned int j1 = (unsigned int)q.y;
        unsigned int j2 = (unsigned int)q.z;
        unsigned int j3 = (unsigned int)q.w;
        unsigned int base = v * 4u;

        ushort4 r;
        if (j0 < N_POS) { r.x = 0xFFFFu; g_pos[j0] = val[base + 0]; }
        else            { r.x = (unsigned short)((j0 - N_POS) / N_NEG); }
        if (j1 < N_POS) { r.y = 0xFFFFu; g_pos[j1] = val[base + 1]; }
        else            { r.y = (unsigned short)((j1 - N_POS) / N_NEG); }
        if (j2 < N_POS) { r.z = 0xFFFFu; g_pos[j2] = val[base + 2]; }
        else            { r.z = (unsigned short)((j2 - N_POS) / N_NEG); }
        if (j3 < N_POS) { r.w = 0xFFFFu; g_pos[j3] = val[base + 3]; }
        else            { r.w = (unsigned short)((j3 - N_POS) / N_NEG); }

        rid4[v] = r;                        // default policy: L2-resident
    }
}

// ---------------------------------------------------------------------------
// Pass 2 (R4 loop + cache hints): val via STREAMING loads (evict-first, so
// the 131MB val stream does not evict the L2-resident rowids); rowid via
// __ldca (expect L2 hit). Minority-side counting:
//   p >  0 -> count (v >  p);  p <= 0 -> count (v <= p)
// inc = (v > p) XOR (p <= 0); fixed up in pass 3. Per-row total <= 4000 so
// packed u16 halves never overflow. 48KB static smem -> 4 blocks/SM, 1 wave.
// ---------------------------------------------------------------------------
__global__ void __launch_bounds__(P2_THREADS) mrr_pass2(const float* __restrict__ val)
{
    __shared__ float        s_pos[N_POS];       // 32768 B
    __shared__ unsigned int s_hist[HIST_WORDS]; // 16384 B

    const int t = threadIdx.x;
    for (int i = t; i < N_POS; i += P2_THREADS)      s_pos[i]  = g_pos[i];
    for (int i = t; i < HIST_WORDS; i += P2_THREADS) s_hist[i] = 0u;
    __syncthreads();

    const unsigned int tid = blockIdx.x * P2_THREADS + t;
    const unsigned int stride = gridDim.x * P2_THREADS;
    const float4*  __restrict__ v4 = (const float4*)val;
    const ushort4* __restrict__ r4 = (const ushort4*)g_rowid;

    #pragma unroll 2
    for (unsigned int v = tid; v < N_VEC; v += stride) {
        float4  f = __ldcs(&v4[v]);    // streaming: don't evict rowids from L2
        ushort4 r = __ldca(&r4[v]);    // expect L2 hit
        {
            float p = s_pos[r.x & 0x1FFFu];
            if (r.x != 0xFFFFu && ((f.x > p) != (p <= 0.0f)))
                atomicAdd(&s_hist[r.x >> 1], 1u << ((r.x & 1u) << 4));
        }
        {
            float p = s_pos[r.y & 0x1FFFu];
            if (r.y != 0xFFFFu && ((f.y > p) != (p <= 0.0f)))
                atomicAdd(&s_hist[r.y >> 1], 1u << ((r.y & 1u) << 4));
        }
        {
            float p = s_pos[r.z & 0x1FFFu];
            if (r.z != 0xFFFFu && ((f.z > p) != (p <= 0.0f)))
                atomicAdd(&s_hist[r.z >> 1], 1u << ((r.z & 1u) << 4));
        }
        {
            float p = s_pos[r.w & 0x1FFFu];
            if (r.w != 0xFFFFu && ((f.w > p) != (p <= 0.0f)))
                atomicAdd(&s_hist[r.w >> 1], 1u << ((r.w & 1u) << 4));
        }
    }
    __syncthreads();

    // R4-proven flush: whole-word atomic add (halves can't carry, <=4000).
    for (int i = t; i < HIST_WORDS; i += P2_THREADS) {
        unsigned int h = s_hist[i];
        if (h) atomicAdd(&g_hist[i], h);
    }
}

// ---------------------------------------------------------------------------
// Pass 3 (R4 + minority fixup): ranks -> sample_mrr, fixed-order mean.
// out[0] = mrr, out[1..8192] = sample_mrr
// ---------------------------------------------------------------------------
__global__ void __launch_bounds__(1024) mrr_pass3(float* __restrict__ out)
{
    __shared__ double ssum[1024];
    const int t = threadIdx.x;
    double local = 0.0;
    for (int r = t; r < N_POS; r += 1024) {
        unsigned int h = g_hist[r >> 1];
        unsigned int c = (r & 1) ? (h >> 16) : (h & 0xFFFFu);
        float p = g_pos[r];
        unsigned int cnt_gt = (p > 0.0f) ? c : (N_NEG - c);
        float s = 1.0f / (float)(1u + cnt_gt);
        out[1 + r] = s;
        local += (double)s;
    }
    ssum[t] = local;
    __syncthreads();
    for (int off = 512; off > 0; off >>= 1) {
        if (t < off) ssum[t] += ssum[t + off];
        __syncthreads();
    }
    if (t == 0) out[0] = (float)(ssum[0] / (double)N_POS);
}

extern "C" void kernel_launch(void* const* d_in, const int* in_sizes, int n_in,
                              void* d_out, int out_size)
{
    const float* val = (const float*)d_in[0];
    const int*   idx = (const int*)d_in[1];
    float*       out = (float*)d_out;

    mrr_pass1<<<2048, 256>>>(val, idx);
    mrr_pass2<<<P2_BLOCKS, P2_THREADS>>>(val);
    mrr_pass3<<<1, 1024>>>(out);
}